// round 16
// baseline (speedup 1.0000x reference)
#include <cuda_runtime.h>
#include <cuda_bf16.h>
#include <cuda_fp16.h>
#include <math.h>
#include <stdint.h>

#define NQ   2048
#define NKV  2048
#define AD   1024
#define NH   16
#define KE1  1024   // plain fp16 projection (no split)

// gate (fp32) + attention operands (fp16)
__device__ float g_gate[NQ * AD];
__device__ __half g_qh [NQ  * AD];   // [row][h*64+c]
__device__ __half g_kh [NKV * AD];
__device__ __half g_vhT[AD * NKV];   // [h*64+vd][key]  (transposed)

// fp16 operands for the projection GEMMs
__device__ __half g_aq[NQ  * KE1];   // [m][k]
__device__ __half g_am[NKV * KE1];
__device__ __half g_wq[AD * KE1];    // [n][k] (transposed W)
__device__ __half g_wk[AD * KE1];
__device__ __half g_wv[AD * KE1];
__device__ __half g_wg[AD * KE1];

__device__ __forceinline__ uint32_t pack_f16x2(float x, float y) {
    __half2 h = __floats2half2_rn(x, y);   // x -> low, y -> high
    return *(uint32_t*)&h;
}

__device__ __forceinline__ void cp16(uint32_t dst, const void* src) {
    asm volatile("cp.async.cg.shared.global [%0], [%1], 16;\n" :: "r"(dst), "l"(src));
}
#define CP_COMMIT() asm volatile("cp.async.commit_group;\n" ::: "memory")
#define CP_WAIT1()  asm volatile("cp.async.wait_group 1;\n" ::: "memory")
#define CP_WAIT0()  asm volatile("cp.async.wait_group 0;\n" ::: "memory")

// fp16 HMMA
__device__ __forceinline__ void mma16816h(
    float c[4], uint32_t a0, uint32_t a1, uint32_t a2, uint32_t a3,
    uint32_t b0, uint32_t b1)
{
    asm volatile(
        "mma.sync.aligned.m16n8k16.row.col.f32.f16.f16.f32 "
        "{%0,%1,%2,%3}, {%4,%5,%6,%7}, {%8,%9}, {%0,%1,%2,%3};"
        : "+f"(c[0]), "+f"(c[1]), "+f"(c[2]), "+f"(c[3])
        : "r"(a0), "r"(a1), "r"(a2), "r"(a3), "r"(b0), "r"(b1));
}

__device__ __forceinline__ void ldsm4(
    uint32_t& r0, uint32_t& r1, uint32_t& r2, uint32_t& r3, uint32_t addr)
{
    asm volatile("ldmatrix.sync.aligned.m8n8.x4.shared.b16 {%0,%1,%2,%3}, [%4];"
                 : "=r"(r0), "=r"(r1), "=r"(r2), "=r"(r3) : "r"(addr));
}

// ---------------------------------------------------------------------------
// Convert activations: x -> fp16 (round-to-nearest).
// ---------------------------------------------------------------------------
__global__ __launch_bounds__(256) void conv_a_kernel(
    const float* __restrict__ src0, const float* __restrict__ src1)
{
    const float* src = blockIdx.y ? src1 : src0;
    __half* dst = blockIdx.y ? g_am : g_aq;
    const int idx = blockIdx.x * 256 + threadIdx.x;
    const int r = idx >> 8;
    const int c = (idx & 255) << 2;
    float4 x = *(const float4*)(src + (size_t)r * 1024 + c);
    uint2 hv;
    hv.x = pack_f16x2(x.x, x.y);
    hv.y = pack_f16x2(x.z, x.w);
    *(uint2*)(dst + (size_t)r * KE1 + c) = hv;
}

// ---------------------------------------------------------------------------
// Convert + transpose weights: W[k][n] -> Wt[n][k] fp16.
// ---------------------------------------------------------------------------
__global__ void conv_w_kernel(const float* __restrict__ w0, const float* __restrict__ w1,
                              const float* __restrict__ w2, const float* __restrict__ w3)
{
    __shared__ float sm[32][33];
    const float* W; __half* Wt;
    switch (blockIdx.z) {
        case 0:  W = w0; Wt = g_wq; break;
        case 1:  W = w1; Wt = g_wk; break;
        case 2:  W = w2; Wt = g_wv; break;
        default: W = w3; Wt = g_wg; break;
    }
    const int n0 = blockIdx.x * 32;
    const int k0 = blockIdx.y * 32;
    const int tx = threadIdx.x, ty = threadIdx.y;
    sm[ty][tx] = W[(size_t)(k0 + ty) * 1024 + n0 + tx];
    __syncthreads();
    Wt[(size_t)(n0 + ty) * KE1 + k0 + tx] = __float2half_rn(sm[tx][ty]);
}

// ---------------------------------------------------------------------------
// fp16 HMMA projection GEMM (unchanged from round 15): cp.async 3-stage,
// K-tile=64, 16 K-tiles (K=1024). Epilogues emit fp16 attention operands.
// ---------------------------------------------------------------------------
#define STAGE_EL 18432
#define PIPE_SMEM_BYTES (3 * STAGE_EL * 2)   // 110,592 B

__global__ __launch_bounds__(256, 2) void proj_mma_kernel(const float* __restrict__ qb)
{
    extern __shared__ __half ps[];
    const uint32_t sbase = (uint32_t)__cvta_generic_to_shared(ps);

    const int tid  = threadIdx.x;
    const int lane = tid & 31;
    const int wid  = tid >> 5;
    const int wm0  = (wid >> 2) * 64;
    const int wn0  = (wid & 3)  * 32;
    const int z    = blockIdx.z;
    const int n0   = blockIdx.x * 128;
    const int m0   = blockIdx.y * 128;

    const __half *Ag, *Bg;
    switch (z) {
        case 0:  Ag = g_aq; Bg = g_wq; break;
        case 1:  Ag = g_am; Bg = g_wk; break;
        case 2:  Ag = g_am; Bg = g_wv; break;
        default: Ag = g_aq; Bg = g_wg; break;
    }
    const __half* Ab = Ag + (size_t)m0 * KE1;
    const __half* Bb = Bg + (size_t)n0 * KE1;

    const int krow = tid >> 2;
    const int seg  = (tid & 3) * 16;
    const int qr   = lane >> 2;
    const int qc   = (lane & 3) * 2;

    const int g  = lane >> 3;
    const int rr = lane & 7;
    const uint32_t aofs = (uint32_t)((((g & 1) * 8 + rr) * 72 + (g >> 1) * 8) * 2);
    const uint32_t bofs = (uint32_t)(((((g & 2) ? 8 : 0) + rr) * 72 + (g & 1) * 8) * 2);

    auto issue = [&](int t, int s) {
        const int off = t * 64 + seg;
        const __half* a0 = Ab + (size_t)krow * KE1 + off;
        const __half* a1 = Ab + (size_t)(krow + 64) * KE1 + off;
        const __half* b0 = Bb + (size_t)krow * KE1 + off;
        const __half* b1 = Bb + (size_t)(krow + 64) * KE1 + off;
        const uint32_t da = sbase + (uint32_t)(s * STAGE_EL + krow * 72 + seg) * 2;
        cp16(da,          a0); cp16(da + 16,          a0 + 8);
        cp16(da + 9216,   a1); cp16(da + 9216 + 16,   a1 + 8);
        cp16(da + 18432,  b0); cp16(da + 18432 + 16,  b0 + 8);
        cp16(da + 27648,  b1); cp16(da + 27648 + 16,  b1 + 8);
        CP_COMMIT();
    };

    issue(0, 0);
    issue(1, 1);

    float acc[4][4][4] = {};
    uint32_t af[2][4][4], bf[2][4][2];

    for (int t = 0; t < 16; t++) {
        const int s = t % 3;
        if (t < 15) CP_WAIT1(); else CP_WAIT0();
        __syncthreads();
        if (t + 2 < 16) issue(t + 2, (t + 2) % 3);

        const uint32_t stA = sbase + (uint32_t)(s * STAGE_EL) * 2;
        const uint32_t stB = stA + 18432;

        auto ldfrags = [&](int buf, int kk) {
            const uint32_t kb = (uint32_t)(kk * 32);
            #pragma unroll
            for (int mt = 0; mt < 4; mt++) {
                const uint32_t a = stA + aofs + (uint32_t)((wm0 + mt * 16) * 144) + kb;
                ldsm4(af[buf][mt][0], af[buf][mt][1], af[buf][mt][2], af[buf][mt][3], a);
            }
            #pragma unroll
            for (int p = 0; p < 2; p++) {
                const uint32_t a = stB + bofs + (uint32_t)((wn0 + p * 16) * 144) + kb;
                ldsm4(bf[buf][2*p][0], bf[buf][2*p][1],
                      bf[buf][2*p+1][0], bf[buf][2*p+1][1], a);
            }
        };

        ldfrags(0, 0);
        #pragma unroll
        for (int kk = 0; kk < 4; kk++) {
            const int b = kk & 1;
            if (kk < 3) ldfrags(b ^ 1, kk + 1);
            #pragma unroll
            for (int mt = 0; mt < 4; mt++)
                #pragma unroll
                for (int nt = 0; nt < 4; nt++)
                    mma16816h(acc[mt][nt],
                              af[b][mt][0], af[b][mt][1], af[b][mt][2], af[b][mt][3],
                              bf[b][nt][0], bf[b][nt][1]);
        }
    }

    #pragma unroll
    for (int mt = 0; mt < 4; mt++) {
        #pragma unroll
        for (int nt = 0; nt < 4; nt++) {
            const int rg0 = m0 + wm0 + mt * 16 + qr;
            const int cg  = n0 + wn0 + nt * 8 + qc;
            float v[4] = {acc[mt][nt][0], acc[mt][nt][1],
                          acc[mt][nt][2], acc[mt][nt][3]};
            if (z == 0) {
                const float b0 = qb[cg], b1 = qb[cg + 1];
                v[0] = (v[0] + b0) * 0.125f; v[1] = (v[1] + b1) * 0.125f;
                v[2] = (v[2] + b0) * 0.125f; v[3] = (v[3] + b1) * 0.125f;
                *(uint32_t*)&g_qh[(size_t)rg0 * 1024 + cg]       = pack_f16x2(v[0], v[1]);
                *(uint32_t*)&g_qh[(size_t)(rg0 + 8) * 1024 + cg] = pack_f16x2(v[2], v[3]);
            } else if (z == 1) {
                *(uint32_t*)&g_kh[(size_t)rg0 * 1024 + cg]       = pack_f16x2(v[0], v[1]);
                *(uint32_t*)&g_kh[(size_t)(rg0 + 8) * 1024 + cg] = pack_f16x2(v[2], v[3]);
            } else if (z == 2) {
                #pragma unroll
                for (int j = 0; j < 4; j++) {
                    const int col = cg + (j & 1);
                    const int row = rg0 + (j >> 1) * 8;
                    g_vhT[(size_t)col * NKV + row] = __float2half_rn(v[j]);
                }
            } else {
                #pragma unroll
                for (int j = 0; j < 4; j++)
                    v[j] = 1.0f / (1.0f + __expf(-v[j]));
                *(float2*)(g_gate + (size_t)rg0 * 1024 + cg)       = make_float2(v[0], v[1]);
                *(float2*)(g_gate + (size_t)(rg0 + 8) * 1024 + cg) = make_float2(v[2], v[3]);
            }
        }
    }
}

// ---------------------------------------------------------------------------
// fp16 HMMA flash attention v3: 4 warps x 32 q-rows (two 16-row halves per
// warp) -- every k/v ldsm4 feeds 4 MMAs (2 per half), halving smem/L1 read
// traffic vs the 8-warp layout. 128 threads, 2 CTA/SM. 1-term QK + 1-term PV,
// fixed-shift softmax exp(s-4), bias hidden behind QK, cp.async 3-stage.
// Stage layout (el): kh [64][72] at 0, vh [64][72] at 4608.
// ---------------------------------------------------------------------------
#define SOFTMAX_SHIFT 4.0f
#define ATT_STAGE_EL 9216
#define ATT_SMEM_BYTES (3 * ATT_STAGE_EL * 2)   // 55,296 B

__global__ __launch_bounds__(128, 2) void attn_kernel(
    const float* __restrict__ bias,
    const float* __restrict__ gate, float* __restrict__ out)
{
    extern __shared__ __half sb[];
    const uint32_t sbase = (uint32_t)__cvta_generic_to_shared(sb);

    const int tid  = threadIdx.x;
    const int lane = tid & 31;
    const int wid  = tid >> 5;          // 0..3
    const int qr   = lane >> 2;
    const int qc   = (lane & 3) * 2;
    const int h    = blockIdx.y;
    const int q0   = blockIdx.x * 128;
    const int w32  = wid * 32;

    const int g  = lane >> 3;
    const int rr = lane & 7;
    const uint32_t bofs = (uint32_t)(((((g & 2) ? 8 : 0) + rr) * 72 + (g & 1) * 8) * 2);

    // q fragments for both 16-row halves, register-resident
    uint32_t qah[2][16];
    #pragma unroll
    for (int mh = 0; mh < 2; mh++) {
        const size_t r0 = (size_t)(q0 + w32 + mh * 16 + qr) * 1024 + h * 64;
        const size_t r1 = r0 + 8 * 1024;
        #pragma unroll
        for (int ks = 0; ks < 4; ks++) {
            const int c = ks * 16 + qc;
            qah[mh][ks * 4 + 0] = *(const uint32_t*)&g_qh[r0 + c];
            qah[mh][ks * 4 + 1] = *(const uint32_t*)&g_qh[r1 + c];
            qah[mh][ks * 4 + 2] = *(const uint32_t*)&g_qh[r0 + c + 8];
            qah[mh][ks * 4 + 3] = *(const uint32_t*)&g_qh[r1 + c + 8];
        }
    }

    // cp.async mapping: 128 threads, 2 threads per 64-el row
    const int krow = tid >> 1;          // 0..63
    const int seg  = (tid & 1) * 32;    // 0 or 32 (elements)

    auto issue = [&](int t, int s) {
        const int kt = t * 64;
        const __half* kh = g_kh + (size_t)(kt + krow) * 1024 + h * 64 + seg;
        const __half* vh = g_vhT + (size_t)(h * 64 + krow) * NKV + kt + seg;
        const uint32_t db = sbase + (uint32_t)(s * ATT_STAGE_EL + krow * 72 + seg) * 2;
        #pragma unroll
        for (int j = 0; j < 4; j++) {
            cp16(db + j * 16,        kh + j * 8);
            cp16(db + 9216 + j * 16, vh + j * 8);
        }
        CP_COMMIT();
    };

    issue(0, 0);
    issue(1, 1);

    float lsum[2][2] = {};
    float oacc[2][8][4] = {};

    for (int t = 0; t < 32; t++) {
        const int s = t % 3;
        const int kt = t * 64;
        if (t < 31) CP_WAIT1(); else CP_WAIT0();
        __syncthreads();
        if (t + 2 < 32) issue(t + 2, (t + 2) % 3);

        const uint32_t st   = sbase + (uint32_t)(s * ATT_STAGE_EL) * 2;
        const uint32_t kh_b = st + bofs;
        const uint32_t vh_b = kh_b + 9216;

        // ---- bias A (keys 0..31, both halves), covered by QK phase A
        float2 ba[2][4][2];
        #pragma unroll
        for (int mh = 0; mh < 2; mh++) {
            const size_t bb = ((size_t)h * NQ + q0 + w32 + mh * 16 + qr) * NKV + kt + qc;
            #pragma unroll
            for (int nt = 0; nt < 4; nt++) {
                ba[mh][nt][0] = *(const float2*)(bias + bb + nt * 8);
                ba[mh][nt][1] = *(const float2*)(bias + bb + 8 * NKV + nt * 8);
            }
        }

        float sacc[2][8][4];
        #pragma unroll
        for (int mh = 0; mh < 2; mh++)
            #pragma unroll
            for (int i = 0; i < 8; i++)
                #pragma unroll
                for (int j = 0; j < 4; j++) sacc[mh][i][j] = 0.0f;

        // ---- QK keys 0..31 (p = 0,1): each ldsm4 feeds both halves
        #pragma unroll
        for (int p = 0; p < 2; p++) {
            #pragma unroll
            for (int ks = 0; ks < 4; ks++) {
                const uint32_t o = (uint32_t)(p * 2304 + ks * 32);
                uint32_t h0, h1, h2, h3;
                ldsm4(h0, h1, h2, h3, kh_b + o);
                #pragma unroll
                for (int mh = 0; mh < 2; mh++) {
                    const uint32_t a0 = qah[mh][ks*4+0], a1 = qah[mh][ks*4+1],
                                   a2 = qah[mh][ks*4+2], a3 = qah[mh][ks*4+3];
                    mma16816h(sacc[mh][2*p],   a0, a1, a2, a3, h0, h1);
                    mma16816h(sacc[mh][2*p+1], a0, a1, a2, a3, h2, h3);
                }
            }
        }
        // fold bias A
        #pragma unroll
        for (int mh = 0; mh < 2; mh++)
            #pragma unroll
            for (int nt = 0; nt < 4; nt++) {
                sacc[mh][nt][0] += ba[mh][nt][0].x; sacc[mh][nt][1] += ba[mh][nt][0].y;
                sacc[mh][nt][2] += ba[mh][nt][1].x; sacc[mh][nt][3] += ba[mh][nt][1].y;
            }
        // bias B (keys 32..63), covered by QK phase B
        #pragma unroll
        for (int mh = 0; mh < 2; mh++) {
            const size_t bb = ((size_t)h * NQ + q0 + w32 + mh * 16 + qr) * NKV + kt + qc;
            #pragma unroll
            for (int nt = 0; nt < 4; nt++) {
                ba[mh][nt][0] = *(const float2*)(bias + bb + (4 + nt) * 8);
                ba[mh][nt][1] = *(const float2*)(bias + bb + 8 * NKV + (4 + nt) * 8);
            }
        }
        // ---- QK keys 32..63 (p = 2,3)
        #pragma unroll
        for (int p = 2; p < 4; p++) {
            #pragma unroll
            for (int ks = 0; ks < 4; ks++) {
                const uint32_t o = (uint32_t)(p * 2304 + ks * 32);
                uint32_t h0, h1, h2, h3;
                ldsm4(h0, h1, h2, h3, kh_b + o);
                #pragma unroll
                for (int mh = 0; mh < 2; mh++) {
                    const uint32_t a0 = qah[mh][ks*4+0], a1 = qah[mh][ks*4+1],
                                   a2 = qah[mh][ks*4+2], a3 = qah[mh][ks*4+3];
                    mma16816h(sacc[mh][2*p],   a0, a1, a2, a3, h0, h1);
                    mma16816h(sacc[mh][2*p+1], a0, a1, a2, a3, h2, h3);
                }
            }
        }

        // ---- exp + pack keys 0..31 (both halves)
        uint32_t pah[2][2][4];
        #pragma unroll
        for (int mh = 0; mh < 2; mh++) {
            #pragma unroll
            for (int kv = 0; kv < 2; kv++) {
                float e00 = __expf(sacc[mh][2*kv][0]   - SOFTMAX_SHIFT);
                float e01 = __expf(sacc[mh][2*kv][1]   - SOFTMAX_SHIFT);
                float e02 = __expf(sacc[mh][2*kv][2]   - SOFTMAX_SHIFT);
                float e03 = __expf(sacc[mh][2*kv][3]   - SOFTMAX_SHIFT);
                float e10 = __expf(sacc[mh][2*kv+1][0] - SOFTMAX_SHIFT);
                float e11 = __expf(sacc[mh][2*kv+1][1] - SOFTMAX_SHIFT);
                float e12 = __expf(sacc[mh][2*kv+1][2] - SOFTMAX_SHIFT);
                float e13 = __expf(sacc[mh][2*kv+1][3] - SOFTMAX_SHIFT);
                lsum[mh][0] += e00 + e01 + e10 + e11;
                lsum[mh][1] += e02 + e03 + e12 + e13;
                pah[mh][kv][0] = pack_f16x2(e00, e01);
                pah[mh][kv][1] = pack_f16x2(e02, e03);
                pah[mh][kv][2] = pack_f16x2(e10, e11);
                pah[mh][kv][3] = pack_f16x2(e12, e13);
            }
        }
        // ---- PV keys 0..31: each v ldsm4 feeds both halves
        #pragma unroll
        for (int kv = 0; kv < 2; kv++) {
            #pragma unroll
            for (int p = 0; p < 4; p++) {
                const uint32_t o = (uint32_t)(p * 2304 + kv * 32);
                uint32_t h0, h1, h2, h3;
                ldsm4(h0, h1, h2, h3, vh_b + o);
                #pragma unroll
                for (int mh = 0; mh < 2; mh++) {
                    mma16816h(oacc[mh][2*p],   pah[mh][kv][0], pah[mh][kv][1],
                              pah[mh][kv][2], pah[mh][kv][3], h0, h1);
                    mma16816h(oacc[mh][2*p+1], pah[mh][kv][0], pah[mh][kv][1],
                              pah[mh][kv][2], pah[mh][kv][3], h2, h3);
                }
            }
        }
        // ---- fold bias B, exp + pack keys 32..63
        #pragma unroll
        for (int mh = 0; mh < 2; mh++)
            #pragma unroll
            for (int nt = 0; nt < 4; nt++) {
                sacc[mh][4+nt][0] += ba[mh][nt][0].x; sacc[mh][4+nt][1] += ba[mh][nt][0].y;
                sacc[mh][4+nt][2] += ba[mh][nt][1].x; sacc[mh][4+nt][3] += ba[mh][nt][1].y;
            }
        #pragma unroll
        for (int mh = 0; mh < 2; mh++) {
            #pragma unroll
            for (int kv = 0; kv < 2; kv++) {
                float e00 = __expf(sacc[mh][4+2*kv][0]   - SOFTMAX_SHIFT);
                float e01 = __expf(sacc[mh][4+2*kv][1]   - SOFTMAX_SHIFT);
                float e02 = __expf(sacc[mh][4+2*kv][2]   - SOFTMAX_SHIFT);
                float e03 = __expf(sacc[mh][4+2*kv][3]   - SOFTMAX_SHIFT);
                float e10 = __expf(sacc[mh][4+2*kv+1][0] - SOFTMAX_SHIFT);
                float e11 = __expf(sacc[mh][4+2*kv+1][1] - SOFTMAX_SHIFT);
                float e12 = __expf(sacc[mh][4+2*kv+1][2] - SOFTMAX_SHIFT);
                float e13 = __expf(sacc[mh][4+2*kv+1][3] - SOFTMAX_SHIFT);
                lsum[mh][0] += e00 + e01 + e10 + e11;
                lsum[mh][1] += e02 + e03 + e12 + e13;
                pah[mh][kv][0] = pack_f16x2(e00, e01);
                pah[mh][kv][1] = pack_f16x2(e02, e03);
                pah[mh][kv][2] = pack_f16x2(e10, e11);
                pah[mh][kv][3] = pack_f16x2(e12, e13);
            }
        }
        // ---- PV keys 32..63
        #pragma unroll
        for (int kv = 0; kv < 2; kv++) {
            #pragma unroll
            for (int p = 0; p < 4; p++) {
                const uint32_t o = (uint32_t)(p * 2304 + (kv + 2) * 32);
                uint32_t h0, h1, h2, h3;
                ldsm4(h0, h1, h2, h3, vh_b + o);
                #pragma unroll
                for (int mh = 0; mh < 2; mh++) {
                    mma16816h(oacc[mh][2*p],   pah[mh][kv][0], pah[mh][kv][1],
                              pah[mh][kv][2], pah[mh][kv][3], h0, h1);
                    mma16816h(oacc[mh][2*p+1], pah[mh][kv][0], pah[mh][kv][1],
                              pah[mh][kv][2], pah[mh][kv][3], h2, h3);
                }
            }
        }
    }

    // final row-sum reduction across the 4 lanes sharing each row
    #pragma unroll
    for (int mh = 0; mh < 2; mh++) {
        #pragma unroll
        for (int i = 0; i < 2; i++) {
            lsum[mh][i] += __shfl_xor_sync(0xffffffffu, lsum[mh][i], 1);
            lsum[mh][i] += __shfl_xor_sync(0xffffffffu, lsum[mh][i], 2);
        }
    }

    // epilogue: normalize + gate; out layout [NQ][H][64]
    #pragma unroll
    for (int mh = 0; mh < 2; mh++) {
        const float inv0 = 1.0f / lsum[mh][0];
        const float inv1 = 1.0f / lsum[mh][1];
        const int r0 = q0 + w32 + mh * 16 + qr;
        const int r1 = r0 + 8;
        #pragma unroll
        for (int nv = 0; nv < 8; nv++) {
            const int c = nv * 8 + qc;
            float2 gv0 = *(const float2*)(gate + (size_t)r0 * 1024 + h * 64 + c);
            float2 gv1 = *(const float2*)(gate + (size_t)r1 * 1024 + h * 64 + c);
            float2 o0 = make_float2(oacc[mh][nv][0] * inv0 * gv0.x,
                                    oacc[mh][nv][1] * inv0 * gv0.y);
            float2 o1 = make_float2(oacc[mh][nv][2] * inv1 * gv1.x,
                                    oacc[mh][nv][3] * inv1 * gv1.y);
            *(float2*)(out + ((size_t)r0 * NH + h) * 64 + c) = o0;
            *(float2*)(out + ((size_t)r1 * NH + h) * 64 + c) = o1;
        }
    }
}

// ---------------------------------------------------------------------------
extern "C" void kernel_launch(void* const* d_in, const int* in_sizes, int n_in,
                              void* d_out, int out_size)
{
    const float* q_data   = (const float*)d_in[0];
    const float* m_data   = (const float*)d_in[1];
    const float* bias     = (const float*)d_in[2];
    const float* query_w  = (const float*)d_in[3];
    const float* query_b  = (const float*)d_in[4];
    const float* key_w    = (const float*)d_in[5];
    const float* value_w  = (const float*)d_in[6];
    const float* gating_w = (const float*)d_in[7];
    float* out = (float*)d_out;

    float* dgate;
    cudaGetSymbolAddress((void**)&dgate, g_gate);

    conv_a_kernel<<<dim3(2048, 2), 256>>>(q_data, m_data);
    conv_w_kernel<<<dim3(32, 32, 4), dim3(32, 32)>>>(query_w, key_w, value_w, gating_w);

    cudaFuncSetAttribute(proj_mma_kernel,
                         cudaFuncAttributeMaxDynamicSharedMemorySize,
                         PIPE_SMEM_BYTES);
    proj_mma_kernel<<<dim3(8, 16, 4), 256, PIPE_SMEM_BYTES>>>(query_b);

    cudaFuncSetAttribute(attn_kernel,
                         cudaFuncAttributeMaxDynamicSharedMemorySize,
                         ATT_SMEM_BYTES);
    attn_kernel<<<dim3(NQ / 128, NH), 128, ATT_SMEM_BYTES>>>(bias, dgate, out);
}